// round 2
// baseline (speedup 1.0000x reference)
#include <cuda_runtime.h>
#include <cuda_bf16.h>
#include <cstdint>

#define BATCH 64
#define LQg   1024
#define LKg   1024
#define DIMg  64
#define BQ    32
#define BK    128
#define NTHREADS 256
#define SS_STRIDE 1032   /* LK + 8  -> breaks 32-bank aliasing for column access */
#define KT_STRIDE 130    /* BK + 2  */
#define V_STRIDE  66     /* DIM + 2 */

/* shared memory layout (floats) */
#define OFF_SS 0
#define SZ_SS  (BQ * SS_STRIDE)          /* 33024 */
#define OFF_Q2 (OFF_SS + SZ_SS)
#define SZ_Q2  (BQ * DIMg * 2)           /* 4096 (float2 duplicated Q) */
#define OFF_KV (OFF_Q2 + SZ_Q2)
#define SZ_KV  (BK * V_STRIDE)           /* 8448 >= 64*130=8320 */
#define SMEM_FLOATS (OFF_KV + SZ_KV)     /* 45568 floats = 182272 B */

__device__ __forceinline__ float2 ffma2(float2 a, float2 b, float2 c) {
    union U { float2 f; unsigned long long u; } ua, ub, uc, ud;
    ua.f = a; ub.f = b; uc.f = c;
    asm("fma.rn.f32x2 %0, %1, %2, %3;" : "=l"(ud.u) : "l"(ua.u), "l"(ub.u), "l"(uc.u));
    return ud.f;
}

__global__ __launch_bounds__(NTHREADS, 1)
void attn_kernel(const float* __restrict__ Q, const float* __restrict__ K,
                 const float* __restrict__ V,
                 const int* __restrict__ qmask, const int* __restrict__ kmask,
                 const int* __restrict__ gmask,
                 float* __restrict__ out_av, float* __restrict__ out_attn)
{
    extern __shared__ float smem[];
    float*  sS  = smem + OFF_SS;
    float2* sQ2 = (float2*)(smem + OFF_Q2);
    float*  sKV = smem + OFF_KV;

    const int tid  = threadIdx.x;
    const int warp = tid >> 5;
    const int lane = tid & 31;
    const int q0   = blockIdx.x * BQ;
    const int b    = blockIdx.y;

    const float NINF = __int_as_float(0xff800000);

    /* ---- load Q tile: scaled by 1/8 and duplicated into float2 lanes ---- */
    {
        const float* Qb = Q + ((size_t)(b * LQg + q0)) * DIMg;
        for (int e = tid; e < BQ * DIMg; e += NTHREADS) {
            float v = Qb[e] * 0.125f;
            sQ2[e] = make_float2(v, v);     /* sQ2[q*DIM + d] */
        }
    }

    const int* kmb = kmask + (size_t)b * LKg;
    const int* mb  = gmask + ((size_t)(b * LQg + q0)) * LKg;

    /* =============== score pass: S = (Q K^T)/8, masked =============== */
    for (int kt = 0; kt < LKg / BK; ++kt) {
        const int kbase = kt * BK;
        __syncthreads();
        /* load K tile transposed: sKt[d][k] = sKV[d*KT_STRIDE + k] */
        {
            const float4* Kb4 = (const float4*)(K + ((size_t)(b * LKg + kbase)) * DIMg);
            for (int e = tid; e < (BK * DIMg) / 4; e += NTHREADS) {
                int k  = e >> 4;
                int d4 = (e & 15) << 2;
                float4 v = Kb4[e];
                float* col = sKV + k;
                col[(d4 + 0) * KT_STRIDE] = v.x;
                col[(d4 + 1) * KT_STRIDE] = v.y;
                col[(d4 + 2) * KT_STRIDE] = v.z;
                col[(d4 + 3) * KT_STRIDE] = v.w;
            }
        }
        __syncthreads();

        /* thread owns k-pairs {2*lane, 2*lane+1} and {64+2*lane, 64+2*lane+1},
           and 4 q rows 4*warp..4*warp+3 */
        float2 acc[4][2];
        #pragma unroll
        for (int i = 0; i < 4; i++) { acc[i][0] = make_float2(0.f,0.f); acc[i][1] = make_float2(0.f,0.f); }

        #pragma unroll 8
        for (int d = 0; d < DIMg; ++d) {
            const float2* krow = (const float2*)(sKV + d * KT_STRIDE);
            float2 k0 = krow[lane];        /* k = 2*lane   */
            float2 k1 = krow[32 + lane];   /* k = 64+2*lane */
            #pragma unroll
            for (int i = 0; i < 4; i++) {
                float2 qv = sQ2[(4 * warp + i) * DIMg + d];   /* broadcast */
                acc[i][0] = ffma2(qv, k0, acc[i][0]);
                acc[i][1] = ffma2(qv, k1, acc[i][1]);
            }
        }

        /* mask + store to sS (masks are 32-bit words: int32 or float32, nonzero == true) */
        #pragma unroll
        for (int c = 0; c < 2; c++) {
            const int kk = c * 64 + 2 * lane;
            const bool km0 = kmb[kbase + kk] != 0;
            const bool km1 = kmb[kbase + kk + 1] != 0;
            #pragma unroll
            for (int i = 0; i < 4; i++) {
                const int qi = 4 * warp + i;
                const int* mrow = mb + (size_t)qi * LKg + kbase;
                float2 v = acc[i][c];
                v.x = (km0 && (mrow[kk] != 0))     ? v.x : NINF;
                v.y = (km1 && (mrow[kk + 1] != 0)) ? v.y : NINF;
                *(float2*)(sS + qi * SS_STRIDE + kbase + kk) = v;
            }
        }
    }
    __syncthreads();

    /* =============== softmax (one warp per row, 4 rows/warp) =============== */
    {
        float* attn_b = out_attn ? (out_attn + ((size_t)(b * LQg + q0)) * LKg) : nullptr;
        for (int r = 0; r < 4; r++) {
            const int qi = 4 * warp + r;
            float* srow = sS + qi * SS_STRIDE;
            float4 vals[8];
            float m = NINF;
            #pragma unroll
            for (int j = 0; j < 8; j++) {
                float4 v = *(float4*)(srow + 4 * (lane + 32 * j));
                vals[j] = v;
                m = fmaxf(m, fmaxf(fmaxf(v.x, v.y), fmaxf(v.z, v.w)));
            }
            #pragma unroll
            for (int off = 16; off; off >>= 1) m = fmaxf(m, __shfl_xor_sync(0xffffffffu, m, off));

            float l = 0.f;
            #pragma unroll
            for (int j = 0; j < 8; j++) {
                float4 v = vals[j];
                v.x = __expf(v.x - m); v.y = __expf(v.y - m);
                v.z = __expf(v.z - m); v.w = __expf(v.w - m);
                l += (v.x + v.y) + (v.z + v.w);
                vals[j] = v;
            }
            #pragma unroll
            for (int off = 16; off; off >>= 1) l += __shfl_xor_sync(0xffffffffu, l, off);

            const float inv = (qmask[(size_t)b * LQg + q0 + qi] != 0) ? (1.0f / l) : 0.0f;
            #pragma unroll
            for (int j = 0; j < 8; j++) {
                float4 v = vals[j];
                v.x *= inv; v.y *= inv; v.z *= inv; v.w *= inv;
                *(float4*)(srow + 4 * (lane + 32 * j)) = v;
                if (attn_b) *(float4*)(attn_b + (size_t)qi * LKg + 4 * (lane + 32 * j)) = v;
            }
        }
    }

    /* =============== PV pass: O = P V  (ksplit=4 over lanes) =============== */
    {
        const int dg = lane & 7;   /* 8 d-groups of 8 */
        const int ks = lane >> 3;  /* 4 k-splits      */
        float2 o[4][4];
        #pragma unroll
        for (int i = 0; i < 4; i++)
            #pragma unroll
            for (int c = 0; c < 4; c++) o[i][c] = make_float2(0.f, 0.f);

        for (int kt = 0; kt < LKg / BK; ++kt) {
            const int kbase = kt * BK;
            __syncthreads();
            /* load V tile: sV[k][d] = sKV[k*V_STRIDE + d] */
            {
                const float4* Vb4 = (const float4*)(V + ((size_t)(b * LKg + kbase)) * DIMg);
                for (int e = tid; e < (BK * DIMg) / 4; e += NTHREADS) {
                    int k  = e >> 4;
                    int d4 = (e & 15) << 2;
                    float4 v = Vb4[e];
                    float* row = sKV + k * V_STRIDE + d4;
                    *(float2*)(row)     = make_float2(v.x, v.y);
                    *(float2*)(row + 2) = make_float2(v.z, v.w);
                }
            }
            __syncthreads();

            for (int kk = ks; kk < BK; kk += 4) {
                const float* vrow = sKV + kk * V_STRIDE + 8 * dg;
                float2 v0 = *(const float2*)(vrow);
                float2 v1 = *(const float2*)(vrow + 2);
                float2 v2 = *(const float2*)(vrow + 4);
                float2 v3 = *(const float2*)(vrow + 6);
                #pragma unroll
                for (int i = 0; i < 4; i++) {
                    float  p  = sS[(4 * warp + i) * SS_STRIDE + kbase + kk];
                    float2 p2 = make_float2(p, p);
                    o[i][0] = ffma2(p2, v0, o[i][0]);
                    o[i][1] = ffma2(p2, v1, o[i][1]);
                    o[i][2] = ffma2(p2, v2, o[i][2]);
                    o[i][3] = ffma2(p2, v3, o[i][3]);
                }
            }
        }

        /* reduce across the 4 k-splits (lane stride 8) */
        #pragma unroll
        for (int off = 8; off <= 16; off <<= 1) {
            #pragma unroll
            for (int i = 0; i < 4; i++)
                #pragma unroll
                for (int c = 0; c < 4; c++) {
                    o[i][c].x += __shfl_xor_sync(0xffffffffu, o[i][c].x, off);
                    o[i][c].y += __shfl_xor_sync(0xffffffffu, o[i][c].y, off);
                }
        }

        if (ks == 0 && out_av) {
            #pragma unroll
            for (int i = 0; i < 4; i++) {
                float* orow = out_av + ((size_t)(b * LQg + q0 + 4 * warp + i)) * DIMg + 8 * dg;
                *(float2*)(orow)     = o[i][0];
                *(float2*)(orow + 2) = o[i][1];
                *(float2*)(orow + 4) = o[i][2];
                *(float2*)(orow + 6) = o[i][3];
            }
        }
    }
}

extern "C" void kernel_launch(void* const* d_in, const int* in_sizes, int n_in,
                              void* d_out, int out_size) {
    const float* Q  = (const float*)d_in[0];
    const float* K  = (const float*)d_in[1];
    const float* V  = (const float*)d_in[2];
    const int*   qm = (const int*)d_in[3];
    const int*   km = (const int*)d_in[4];
    const int*   mk = (const int*)d_in[5];

    const long long NAV  = (long long)BATCH * LQg * DIMg;   /*  4,194,304 */
    const long long NATT = (long long)BATCH * LQg * LKg;    /* 67,108,864 */

    float* out  = (float*)d_out;
    float* av   = nullptr;
    float* attn = nullptr;
    if ((long long)out_size == NAV + NATT)      { av = out; attn = out + NAV; }
    else if ((long long)out_size == NAV)        { av = out; }
    else if ((long long)out_size == NATT)       { attn = out; }
    else                                        { av = out; attn = out + NAV; }

    const size_t smem_bytes = (size_t)SMEM_FLOATS * sizeof(float);
    cudaFuncSetAttribute(attn_kernel, cudaFuncAttributeMaxDynamicSharedMemorySize,
                         (int)smem_bytes);

    dim3 grid(LQg / BQ, BATCH);
    attn_kernel<<<grid, NTHREADS, smem_bytes>>>(Q, K, V, qm, km, mk, av, attn);
}

// round 5
// speedup vs baseline: 2.2644x; 2.2644x over previous
#include <cuda_runtime.h>
#include <cuda_bf16.h>
#include <cstdint>

#define BATCH 64
#define LQS   1024
#define LKS   1024
#define DIMS  64
#define NTHREADS 256
#define BKT   64        /* keys per tile */
#define NTILE (LKS / BKT)

/* ---- shared memory byte offsets (tile bases 1024-aligned) ---- */
#define OFF_SL  0                       /* 128 floats: per-row inv */
#define OFF_QHI 1024
#define OFF_QLO (OFF_QHI + 16384)
#define OFF_KHI (OFF_QLO + 16384)
#define OFF_KLO (OFF_KHI + 8192)
#define OFF_VHI (OFF_KLO + 8192)
#define OFF_VLO (OFF_VHI + 8192)
#define SMEM_BYTES (OFF_VLO + 8192)     /* 66560 B */

#define SWZ(x) ((x) ^ (((x) >> 3) & 0x70))

/* ------------------------- helpers ------------------------- */
__device__ __forceinline__ uint32_t smem_u32(const void* p) {
    uint32_t a;
    asm("{ .reg .u64 t; cvta.to.shared.u64 t, %1; cvt.u32.u64 %0, t; }" : "=r"(a) : "l"(p));
    return a;
}
__device__ __forceinline__ void ldm_x4(uint32_t* d, uint32_t a) {
    asm volatile("ldmatrix.sync.aligned.m8n8.x4.shared.b16 {%0,%1,%2,%3}, [%4];"
        : "=r"(d[0]), "=r"(d[1]), "=r"(d[2]), "=r"(d[3]) : "r"(a));
}
__device__ __forceinline__ void ldm_x2(uint32_t* d, uint32_t a) {
    asm volatile("ldmatrix.sync.aligned.m8n8.x2.shared.b16 {%0,%1}, [%2];"
        : "=r"(d[0]), "=r"(d[1]) : "r"(a));
}
__device__ __forceinline__ void ldm_x2t(uint32_t* d, uint32_t a) {
    asm volatile("ldmatrix.sync.aligned.m8n8.x2.trans.shared.b16 {%0,%1}, [%2];"
        : "=r"(d[0]), "=r"(d[1]) : "r"(a));
}
__device__ __forceinline__ void mma16816(float* c, const uint32_t* a, const uint32_t* b) {
    asm volatile("mma.sync.aligned.m16n8k16.row.col.f32.bf16.bf16.f32 "
        "{%0,%1,%2,%3}, {%4,%5,%6,%7}, {%8,%9}, {%0,%1,%2,%3};"
        : "+f"(c[0]), "+f"(c[1]), "+f"(c[2]), "+f"(c[3])
        : "r"(a[0]), "r"(a[1]), "r"(a[2]), "r"(a[3]), "r"(b[0]), "r"(b[1]));
}
__device__ __forceinline__ uint32_t pack2bf(float a, float b) {
    __nv_bfloat16 ha = __float2bfloat16(a), hb = __float2bfloat16(b);
    return (uint32_t)__bfloat16_as_ushort(ha) | ((uint32_t)__bfloat16_as_ushort(hb) << 16);
}
/* split float2 -> hi word + residual-lo word */
__device__ __forceinline__ void split2(float2 v, uint32_t& hw, uint32_t& lw) {
    __nv_bfloat16 h0 = __float2bfloat16(v.x), h1 = __float2bfloat16(v.y);
    hw = (uint32_t)__bfloat16_as_ushort(h0) | ((uint32_t)__bfloat16_as_ushort(h1) << 16);
    lw = pack2bf(v.x - __bfloat162float(h0), v.y - __bfloat162float(h1));
}

/* ============================ main kernel ============================ */
__global__ __launch_bounds__(NTHREADS, 1)
void attn_mma_kernel(const float* __restrict__ Qg, const float* __restrict__ Kg,
                     const float* __restrict__ Vg,
                     const int* __restrict__ qmask, const int* __restrict__ kmask,
                     const int* __restrict__ gmask,
                     float* __restrict__ out_av, float* __restrict__ out_attn)
{
    extern __shared__ char smem[];
    const uint32_t sb = smem_u32(smem);
    float* sL = (float*)(smem + OFF_SL);

    const int tid  = threadIdx.x;
    const int warp = tid >> 5;
    const int lane = tid & 31;
    const int l16  = lane & 15;
    const int qg   = lane & 3;      /* quad col group  */
    const int r    = lane >> 2;     /* quad row (0-7)  */
    const int b    = blockIdx.y;
    const int q0   = blockIdx.x * 128;

    /* ---- stage Q (scaled 1/8), split hi/lo, SW128 rows of 128B ---- */
    {
        const float2* Qg2 = (const float2*)(Qg + ((size_t)(b * LQS + q0)) * DIMS);
        for (int i = tid; i < 128 * 32; i += NTHREADS) {
            int row = i >> 5, dp = i & 31;
            float2 v = Qg2[i];
            v.x *= 0.125f; v.y *= 0.125f;
            uint32_t hw, lw; split2(v, hw, lw);
            uint32_t off = SWZ((uint32_t)(row * 128 + dp * 4));
            *(uint32_t*)(smem + OFF_QHI + off) = hw;
            *(uint32_t*)(smem + OFF_QLO + off) = lw;
        }
    }
    __syncthreads();

    /* ---- per-warp Q A-fragments (4 k-steps of d, hi+lo) ---- */
    uint32_t qh[4][4], ql[4][4];
    {
        const int qrow = warp * 16 + l16;
        const int cgrp = (lane >> 4) * 16;
        #pragma unroll
        for (int t = 0; t < 4; ++t) {
            uint32_t off = SWZ((uint32_t)(qrow * 128 + t * 32 + cgrp));
            ldm_x4(qh[t], sb + OFF_QHI + off);
            ldm_x4(ql[t], sb + OFF_QLO + off);
        }
    }

    float oc[8][4];
    #pragma unroll
    for (int j = 0; j < 8; ++j)
        #pragma unroll
        for (int c = 0; c < 4; ++c) oc[j][c] = 0.f;
    float l0 = 0.f, l1 = 0.f;

    const int row_r  = warp * 16 + r;
    const int row_r8 = row_r + 8;
    const size_t gq_r  = (size_t)(b * LQS + q0 + row_r);
    const size_t gq_r8 = gq_r + 8;
    const int*  kmb  = kmask + (size_t)b * LKS;
    float* attn_r  = out_attn + gq_r  * LKS;
    float* attn_r8 = out_attn + gq_r8 * LKS;
    const int* gm_r  = gmask + gq_r  * LKS;
    const int* gm_r8 = gmask + gq_r8 * LKS;

    #pragma unroll 1
    for (int kt = 0; kt < NTILE; ++kt) {
        const int kbase = kt * BKT;
        if (kt) __syncthreads();

        /* ---- stage K,V tiles (64x64), split hi/lo ---- */
        {
            const float2* K2 = (const float2*)(Kg + ((size_t)(b * LKS + kbase)) * DIMS);
            const float2* V2 = (const float2*)(Vg + ((size_t)(b * LKS + kbase)) * DIMS);
            for (int i = tid; i < 64 * 32; i += NTHREADS) {
                int row = i >> 5, dp = i & 31;
                uint32_t off = SWZ((uint32_t)(row * 128 + dp * 4));
                uint32_t hw, lw;
                split2(K2[i], hw, lw);
                *(uint32_t*)(smem + OFF_KHI + off) = hw;
                *(uint32_t*)(smem + OFF_KLO + off) = lw;
                split2(V2[i], hw, lw);
                *(uint32_t*)(smem + OFF_VHI + off) = hw;
                *(uint32_t*)(smem + OFF_VLO + off) = lw;
            }
        }
        __syncthreads();

        /* ---- S = Q K^T with bf16 EC (hi*hi + lo*hi + hi*lo) ---- */
        float sc[8][4];
        #pragma unroll
        for (int j = 0; j < 8; ++j)
            #pragma unroll
            for (int c = 0; c < 4; ++c) sc[j][c] = 0.f;

        #pragma unroll
        for (int t = 0; t < 4; ++t) {
            #pragma unroll
            for (int j = 0; j < 8; ++j) {
                uint32_t kh[2], kl[2];
                uint32_t off = SWZ((uint32_t)((j * 8 + (l16 & 7)) * 128 +
                                              t * 32 + (l16 >> 3) * 16));
                ldm_x2(kh, sb + OFF_KHI + off);
                ldm_x2(kl, sb + OFF_KLO + off);
                mma16816(sc[j], qh[t], kh);
                mma16816(sc[j], ql[t], kh);
                mma16816(sc[j], qh[t], kl);
            }
        }

        /* ---- epilogue: mask, exp, row sums, attn store, P pack ---- */
        uint32_t ph_r[8], ph_r8[8], pl_r[8], pl_r8[8];
        #pragma unroll
        for (int j = 0; j < 8; ++j) {
            const int col = kbase + j * 8 + 2 * qg;
            int2 km = *(const int2*)(kmb + col);
            int2 g0 = *(const int2*)(gm_r + col);
            int2 g1 = *(const int2*)(gm_r8 + col);
            float e0 = (km.x && g0.x) ? __expf(sc[j][0]) : 0.f;
            float e1 = (km.y && g0.y) ? __expf(sc[j][1]) : 0.f;
            float e2 = (km.x && g1.x) ? __expf(sc[j][2]) : 0.f;
            float e3 = (km.y && g1.y) ? __expf(sc[j][3]) : 0.f;
            l0 += e0 + e1; l1 += e2 + e3;
            *(float2*)(attn_r  + col) = make_float2(e0, e1);
            *(float2*)(attn_r8 + col) = make_float2(e2, e3);
            uint32_t hw, lw;
            split2(make_float2(e0, e1), hw, lw);  ph_r[j]  = hw; pl_r[j]  = lw;
            split2(make_float2(e2, e3), hw, lw);  ph_r8[j] = hw; pl_r8[j] = lw;
        }

        /* ---- O += P V with EC (Ph*Vh + Ph*Vl + Pl*Vh) ---- */
        #pragma unroll
        for (int t2 = 0; t2 < 4; ++t2) {
            uint32_t pa_h[4] = { ph_r[2*t2], ph_r8[2*t2], ph_r[2*t2+1], ph_r8[2*t2+1] };
            uint32_t pa_l[4] = { pl_r[2*t2], pl_r8[2*t2], pl_r[2*t2+1], pl_r8[2*t2+1] };
            #pragma unroll
            for (int j2 = 0; j2 < 8; ++j2) {
                uint32_t vh[2], vl[2];
                uint32_t off = SWZ((uint32_t)((t2 * 16 + l16) * 128 + j2 * 16));
                ldm_x2t(vh, sb + OFF_VHI + off);
                ldm_x2t(vl, sb + OFF_VLO + off);
                mma16816(oc[j2], pa_h, vh);
                mma16816(oc[j2], pa_h, vl);
                mma16816(oc[j2], pa_l, vh);
            }
        }
    }

    /* ---- row sums across quad lanes, inv, store attn_value ---- */
    l0 += __shfl_xor_sync(0xffffffffu, l0, 1);
    l0 += __shfl_xor_sync(0xffffffffu, l0, 2);
    l1 += __shfl_xor_sync(0xffffffffu, l1, 1);
    l1 += __shfl_xor_sync(0xffffffffu, l1, 2);
    const float inv0 = (qmask[gq_r]  != 0) ? (1.0f / l0) : 0.0f;
    const float inv1 = (qmask[gq_r8] != 0) ? (1.0f / l1) : 0.0f;
    if (qg == 0) { sL[row_r] = inv0; sL[row_r8] = inv1; }

    {
        float* av_r  = out_av + gq_r  * DIMS;
        float* av_r8 = out_av + gq_r8 * DIMS;
        #pragma unroll
        for (int j2 = 0; j2 < 8; ++j2) {
            const int col = j2 * 8 + 2 * qg;
            *(float2*)(av_r  + col) = make_float2(oc[j2][0] * inv0, oc[j2][1] * inv0);
            *(float2*)(av_r8 + col) = make_float2(oc[j2][2] * inv1, oc[j2][3] * inv1);
        }
    }

    /* ---- fused normalize of this CTA's attn rows (L2-resident) ---- */
    __threadfence_block();
    __syncthreads();
    {
        float4* base = (float4*)(out_attn + ((size_t)(b * LQS + q0)) * LKS);
        for (int i = tid; i < 128 * 256; i += NTHREADS) {
            const float inv = sL[i >> 8];
            float4 v = base[i];
            v.x *= inv; v.y *= inv; v.z *= inv; v.w *= inv;
            base[i] = v;
        }
    }
}

extern "C" void kernel_launch(void* const* d_in, const int* in_sizes, int n_in,
                              void* d_out, int out_size) {
    const float* Q  = (const float*)d_in[0];
    const float* K  = (const float*)d_in[1];
    const float* V  = (const float*)d_in[2];
    const int*   qm = (const int*)d_in[3];
    const int*   km = (const int*)d_in[4];
    const int*   mk = (const int*)d_in[5];

    const long long NAV = (long long)BATCH * LQS * DIMS;
    float* out  = (float*)d_out;
    float* av   = out;
    float* attn = out + NAV;
    (void)out_size; (void)in_sizes; (void)n_in;

    cudaFuncSetAttribute(attn_mma_kernel, cudaFuncAttributeMaxDynamicSharedMemorySize,
                         SMEM_BYTES);
    dim3 grid(LQS / 128, BATCH);
    attn_mma_kernel<<<grid, NTHREADS, SMEM_BYTES>>>(Q, K, V, qm, km, mk, av, attn);
}

// round 6
// speedup vs baseline: 2.7378x; 1.2090x over previous
#include <cuda_runtime.h>
#include <cuda_bf16.h>
#include <cstdint>

#define BATCH 64
#define LQS   1024
#define LKS   1024
#define DIMS  64
#define NTHREADS 256
#define BKT   64        /* keys per tile */
#define NTILE (LKS / BKT)

/* ---- shared memory byte offsets ---- */
#define OFF_SL  0                       /* 128 floats: per-row inv */
#define OFF_QHI 1024
#define OFF_QLO (OFF_QHI + 16384)
#define OFF_KHI (OFF_QLO + 16384)       /* 33792, 1024-aligned */
#define OFF_KLO (OFF_KHI + 8192)
#define OFF_VHI (OFF_KLO + 8192)
#define OFF_VLO (OFF_VHI + 8192)
/* raw staging ring (2 buffers): K fp32, V fp32, gmask slab, kmask */
#define OFF_RK  0
#define OFF_RV  16384
#define OFF_RG  32768                   /* 128 rows x 272 B (68-int stride) */
#define OFF_RKM (32768 + 34816)         /* 67584 */
#define RAW_BYTES (67584 + 256)         /* 67840 */
#define OFF_RAW0 (OFF_VLO + 8192)       /* 66560 */
#define SMEM_BYTES (OFF_RAW0 + 2 * RAW_BYTES)   /* 202240 */

#define SWZ(x) ((x) ^ (((x) >> 3) & 0x70))

/* ------------------------- helpers ------------------------- */
__device__ __forceinline__ uint32_t smem_u32(const void* p) {
    uint32_t a;
    asm("{ .reg .u64 t; cvta.to.shared.u64 t, %1; cvt.u32.u64 %0, t; }" : "=r"(a) : "l"(p));
    return a;
}
__device__ __forceinline__ void cp16(uint32_t d, const void* s) {
    asm volatile("cp.async.cg.shared.global [%0], [%1], 16;" :: "r"(d), "l"(s) : "memory");
}
#define CP_COMMIT() asm volatile("cp.async.commit_group;" ::: "memory")
__device__ __forceinline__ void ldm_x4(uint32_t* d, uint32_t a) {
    asm volatile("ldmatrix.sync.aligned.m8n8.x4.shared.b16 {%0,%1,%2,%3}, [%4];"
        : "=r"(d[0]), "=r"(d[1]), "=r"(d[2]), "=r"(d[3]) : "r"(a));
}
__device__ __forceinline__ void ldm_x4t(uint32_t* d, uint32_t a) {
    asm volatile("ldmatrix.sync.aligned.m8n8.x4.trans.shared.b16 {%0,%1,%2,%3}, [%4];"
        : "=r"(d[0]), "=r"(d[1]), "=r"(d[2]), "=r"(d[3]) : "r"(a));
}
__device__ __forceinline__ void mma16816(float* c, const uint32_t* a, const uint32_t* b) {
    asm volatile("mma.sync.aligned.m16n8k16.row.col.f32.bf16.bf16.f32 "
        "{%0,%1,%2,%3}, {%4,%5,%6,%7}, {%8,%9}, {%0,%1,%2,%3};"
        : "+f"(c[0]), "+f"(c[1]), "+f"(c[2]), "+f"(c[3])
        : "r"(a[0]), "r"(a[1]), "r"(a[2]), "r"(a[3]), "r"(b[0]), "r"(b[1]));
}
__device__ __forceinline__ uint32_t pack2bf(float a, float b) {
    __nv_bfloat16 ha = __float2bfloat16(a), hb = __float2bfloat16(b);
    return (uint32_t)__bfloat16_as_ushort(ha) | ((uint32_t)__bfloat16_as_ushort(hb) << 16);
}
__device__ __forceinline__ void split2(float2 v, uint32_t& hw, uint32_t& lw) {
    __nv_bfloat16 h0 = __float2bfloat16(v.x), h1 = __float2bfloat16(v.y);
    hw = (uint32_t)__bfloat16_as_ushort(h0) | ((uint32_t)__bfloat16_as_ushort(h1) << 16);
    lw = pack2bf(v.x - __bfloat162float(h0), v.y - __bfloat162float(h1));
}

/* ============================ main kernel ============================ */
__global__ __launch_bounds__(NTHREADS, 1)
void attn_mma_kernel(const float* __restrict__ Qg, const float* __restrict__ Kg,
                     const float* __restrict__ Vg,
                     const int* __restrict__ qmask, const int* __restrict__ kmask,
                     const int* __restrict__ gmask,
                     float* __restrict__ out_av, float* __restrict__ out_attn)
{
    extern __shared__ char smem[];
    const uint32_t sb = smem_u32(smem);
    float* sL = (float*)(smem + OFF_SL);

    const int tid  = threadIdx.x;
    const int warp = tid >> 5;
    const int lane = tid & 31;
    const int l16  = lane & 15;
    const int qg   = lane & 3;
    const int r    = lane >> 2;
    const int b    = blockIdx.y;
    const int q0   = blockIdx.x * 128;

    const int*  kmb = kmask + (size_t)b * LKS;
    const int*  gm0 = gmask + ((size_t)(b * LQS + q0)) * LKS;

    /* ---- prefetch tile 0 (K, V, gmask slab, kmask) ---- */
    {
        const uint32_t buf = sb + OFF_RAW0;
        const float4* Ks = (const float4*)(Kg + ((size_t)(b * LKS)) * DIMS);
        const float4* Vs = (const float4*)(Vg + ((size_t)(b * LKS)) * DIMS);
        for (int i = tid; i < 1024; i += NTHREADS) {
            cp16(buf + OFF_RK + i * 16, Ks + i);
            cp16(buf + OFF_RV + i * 16, Vs + i);
        }
        for (int i = tid; i < 2048; i += NTHREADS) {
            int row = i >> 4, c = i & 15;
            cp16(buf + OFF_RG + row * 272 + c * 16, gm0 + (size_t)row * LKS + c * 4);
        }
        if (tid < 16) cp16(buf + OFF_RKM + tid * 16, kmb + tid * 4);
        CP_COMMIT();
    }

    /* ---- stage Q (scaled 1/8), split hi/lo, SW128 ---- */
    {
        const float2* Qg2 = (const float2*)(Qg + ((size_t)(b * LQS + q0)) * DIMS);
        for (int i = tid; i < 128 * 32; i += NTHREADS) {
            int row = i >> 5, dp = i & 31;
            float2 v = Qg2[i];
            v.x *= 0.125f; v.y *= 0.125f;
            uint32_t hw, lw; split2(v, hw, lw);
            uint32_t off = SWZ((uint32_t)(row * 128 + dp * 4));
            *(uint32_t*)(smem + OFF_QHI + off) = hw;
            *(uint32_t*)(smem + OFF_QLO + off) = lw;
        }
    }
    __syncthreads();

    /* ---- per-warp Q A-fragments ---- */
    uint32_t qh[4][4], ql[4][4];
    {
        const int qrow = warp * 16 + l16;
        const int cgrp = (lane >> 4) * 16;
        #pragma unroll
        for (int t = 0; t < 4; ++t) {
            uint32_t off = SWZ((uint32_t)(qrow * 128 + t * 32 + cgrp));
            ldm_x4(qh[t], sb + OFF_QHI + off);
            ldm_x4(ql[t], sb + OFF_QLO + off);
        }
    }

    float oc[8][4];
    #pragma unroll
    for (int j = 0; j < 8; ++j)
        #pragma unroll
        for (int c = 0; c < 4; ++c) oc[j][c] = 0.f;
    float l0 = 0.f, l1 = 0.f;

    const int row_r  = warp * 16 + r;
    const int row_r8 = row_r + 8;
    const size_t gq_r  = (size_t)(b * LQS + q0 + row_r);
    const size_t gq_r8 = gq_r + 8;
    float* attn_r  = out_attn + gq_r  * LKS;
    float* attn_r8 = out_attn + gq_r8 * LKS;

    #pragma unroll 1
    for (int kt = 0; kt < NTILE; ++kt) {
        const int kbase = kt * BKT;
        char* rawp = smem + OFF_RAW0 + (kt & 1) * RAW_BYTES;

        if (kt) __syncthreads();   /* previous tile fully consumed */

        /* ---- prefetch tile kt+1 into other buffer ---- */
        if (kt + 1 < NTILE) {
            const int nb = kbase + BKT;
            const uint32_t buf = sb + OFF_RAW0 + (uint32_t)(((kt + 1) & 1) * RAW_BYTES);
            const float4* Ks = (const float4*)(Kg + ((size_t)(b * LKS + nb)) * DIMS);
            const float4* Vs = (const float4*)(Vg + ((size_t)(b * LKS + nb)) * DIMS);
            for (int i = tid; i < 1024; i += NTHREADS) {
                cp16(buf + OFF_RK + i * 16, Ks + i);
                cp16(buf + OFF_RV + i * 16, Vs + i);
            }
            const int* Gs = gm0 + nb;
            for (int i = tid; i < 2048; i += NTHREADS) {
                int row = i >> 4, c = i & 15;
                cp16(buf + OFF_RG + row * 272 + c * 16, Gs + (size_t)row * LKS + c * 4);
            }
            if (tid < 16) cp16(buf + OFF_RKM + tid * 16, kmb + nb + tid * 4);
            CP_COMMIT();
            asm volatile("cp.async.wait_group 1;" ::: "memory");
        } else {
            asm volatile("cp.async.wait_group 0;" ::: "memory");
        }
        __syncthreads();   /* tile kt raw data visible to all */

        /* ---- convert raw K/V -> bf16 hi/lo tiles ---- */
        {
            const float2* rK2 = (const float2*)(rawp + OFF_RK);
            const float2* rV2 = (const float2*)(rawp + OFF_RV);
            for (int i = tid; i < 2048; i += NTHREADS) {
                int row = i >> 5, dp = i & 31;
                uint32_t off = SWZ((uint32_t)(row * 128 + dp * 4));
                uint32_t hw, lw;
                split2(rK2[i], hw, lw);
                *(uint32_t*)(smem + OFF_KHI + off) = hw;
                *(uint32_t*)(smem + OFF_KLO + off) = lw;
                split2(rV2[i], hw, lw);
                *(uint32_t*)(smem + OFF_VHI + off) = hw;
                *(uint32_t*)(smem + OFF_VLO + off) = lw;
            }
        }
        __syncthreads();

        /* ---- S = Q K^T with bf16 EC (hi*hi + lo*hi + hi*lo) ---- */
        float sc[8][4];
        #pragma unroll
        for (int j = 0; j < 8; ++j)
            #pragma unroll
            for (int c = 0; c < 4; ++c) sc[j][c] = 0.f;

        #pragma unroll
        for (int t = 0; t < 4; ++t) {
            #pragma unroll
            for (int jp = 0; jp < 4; ++jp) {
                uint32_t kh4[4], kl4[4];
                int krow = jp * 16 + (lane & 7) + ((lane >> 4) << 3);
                uint32_t off = SWZ((uint32_t)(krow * 128 + t * 32 + ((lane >> 3) & 1) * 16));
                ldm_x4(kh4, sb + OFF_KHI + off);
                ldm_x4(kl4, sb + OFF_KLO + off);
                mma16816(sc[2*jp],   qh[t], kh4);
                mma16816(sc[2*jp],   ql[t], kh4);
                mma16816(sc[2*jp],   qh[t], kl4);
                mma16816(sc[2*jp+1], qh[t], kh4 + 2);
                mma16816(sc[2*jp+1], ql[t], kh4 + 2);
                mma16816(sc[2*jp+1], qh[t], kl4 + 2);
            }
        }

        /* ---- per 16-key group: epilogue then PV MMAs ---- */
        const int* smKM = (const int*)(rawp + OFF_RKM);
        const int* smG  = (const int*)(rawp + OFF_RG);
        #pragma unroll
        for (int t2 = 0; t2 < 4; ++t2) {
            uint32_t pa_h[4], pa_l[4];
            #pragma unroll
            for (int u = 0; u < 2; ++u) {
                const int j = 2 * t2 + u;
                const int c64 = j * 8 + 2 * qg;
                int2 km = *(const int2*)(smKM + c64);
                int2 g0 = *(const int2*)(smG + row_r  * 68 + c64);
                int2 g1 = *(const int2*)(smG + row_r8 * 68 + c64);
                float e0 = (km.x && g0.x) ? __expf(sc[j][0]) : 0.f;
                float e1 = (km.y && g0.y) ? __expf(sc[j][1]) : 0.f;
                float e2 = (km.x && g1.x) ? __expf(sc[j][2]) : 0.f;
                float e3 = (km.y && g1.y) ? __expf(sc[j][3]) : 0.f;
                l0 += e0 + e1; l1 += e2 + e3;
                *(float2*)(attn_r  + kbase + c64) = make_float2(e0, e1);
                *(float2*)(attn_r8 + kbase + c64) = make_float2(e2, e3);
                uint32_t hw, lw;
                split2(make_float2(e0, e1), hw, lw); pa_h[2*u]   = hw; pa_l[2*u]   = lw;
                split2(make_float2(e2, e3), hw, lw); pa_h[2*u+1] = hw; pa_l[2*u+1] = lw;
            }
            #pragma unroll
            for (int j2p = 0; j2p < 4; ++j2p) {
                uint32_t vh4[4], vl4[4];
                int vrow = t2 * 16 + (lane & 15);
                uint32_t off = SWZ((uint32_t)(vrow * 128 + j2p * 32 + (lane >> 4) * 16));
                ldm_x4t(vh4, sb + OFF_VHI + off);
                ldm_x4t(vl4, sb + OFF_VLO + off);
                mma16816(oc[2*j2p],   pa_h, vh4);
                mma16816(oc[2*j2p],   pa_h, vl4);
                mma16816(oc[2*j2p],   pa_l, vh4);
                mma16816(oc[2*j2p+1], pa_h, vh4 + 2);
                mma16816(oc[2*j2p+1], pa_h, vl4 + 2);
                mma16816(oc[2*j2p+1], pa_l, vh4 + 2);
            }
        }
    }

    /* ---- row sums across quad lanes, inv, store attn_value ---- */
    l0 += __shfl_xor_sync(0xffffffffu, l0, 1);
    l0 += __shfl_xor_sync(0xffffffffu, l0, 2);
    l1 += __shfl_xor_sync(0xffffffffu, l1, 1);
    l1 += __shfl_xor_sync(0xffffffffu, l1, 2);
    const float inv0 = (qmask[gq_r]  != 0) ? (1.0f / l0) : 0.0f;
    const float inv1 = (qmask[gq_r8] != 0) ? (1.0f / l1) : 0.0f;
    if (qg == 0) { sL[row_r] = inv0; sL[row_r8] = inv1; }

    {
        float* av_r  = out_av + gq_r  * DIMS;
        float* av_r8 = out_av + gq_r8 * DIMS;
        #pragma unroll
        for (int j2 = 0; j2 < 8; ++j2) {
            const int col = j2 * 8 + 2 * qg;
            *(float2*)(av_r  + col) = make_float2(oc[j2][0] * inv0, oc[j2][1] * inv0);
            *(float2*)(av_r8 + col) = make_float2(oc[j2][2] * inv1, oc[j2][3] * inv1);
        }
    }

    /* ---- fused normalize of this CTA's attn rows (L2-resident) ---- */
    __threadfence_block();
    __syncthreads();
    {
        float4* base = (float4*)(out_attn + ((size_t)(b * LQS + q0)) * LKS);
        for (int i = tid; i < 128 * 256; i += NTHREADS) {
            const float inv = sL[i >> 8];
            float4 v = base[i];
            v.x *= inv; v.y *= inv; v.z *= inv; v.w *= inv;
            base[i] = v;
        }
    }
}

extern "C" void kernel_launch(void* const* d_in, const int* in_sizes, int n_in,
                              void* d_out, int out_size) {
    const float* Q  = (const float*)d_in[0];
    const float* K  = (const float*)d_in[1];
    const float* V  = (const float*)d_in[2];
    const int*   qm = (const int*)d_in[3];
    const int*   km = (const int*)d_in[4];
    const int*   mk = (const int*)d_in[5];

    const long long NAV = (long long)BATCH * LQS * DIMS;
    float* out  = (float*)d_out;
    float* av   = out;
    float* attn = out + NAV;
    (void)out_size; (void)in_sizes; (void)n_in;

    cudaFuncSetAttribute(attn_mma_kernel, cudaFuncAttributeMaxDynamicSharedMemorySize,
                         SMEM_BYTES);
    dim3 grid(LQS / 128, BATCH);
    attn_mma_kernel<<<grid, NTHREADS, SMEM_BYTES>>>(Q, K, V, qm, km, mk, av, attn);
}

// round 7
// speedup vs baseline: 2.9348x; 1.0720x over previous
#include <cuda_runtime.h>
#include <cuda_bf16.h>
#include <cstdint>

#define BATCH 64
#define LQS   1024
#define LKS   1024
#define DIMS  64
#define NTHREADS 256
#define BKT   64        /* keys per tile */
#define NTILE (LKS / BKT)

/* ---- shared memory byte offsets ---- */
#define OFF_SL   0                       /* 128 floats: per-row inv */
#define OFF_QHI  1024
#define OFF_QLO  (OFF_QHI + 16384)
#define OFF_CONV (OFF_QLO + 16384)       /* 33792; two conv buffers of 32KB */
#define OFFC_KHI 0
#define OFFC_KLO 8192
#define OFFC_VHI 16384
#define OFFC_VLO 24576
#define CONV_BYTES 32768
#define OFF_GM   (OFF_CONV + 2 * CONV_BYTES)  /* 99328; 2 x (128 rows x 272B) */
#define GM_BYTES 34816
#define OFF_KM   (OFF_GM + 2 * GM_BYTES)      /* 168960; 4KB kmask */
#define SMEM_BYTES (OFF_KM + 4096)            /* 173056 */

#define SWZ(x) ((x) ^ (((x) >> 3) & 0x70))

/* ------------------------- helpers ------------------------- */
__device__ __forceinline__ uint32_t smem_u32(const void* p) {
    uint32_t a;
    asm("{ .reg .u64 t; cvta.to.shared.u64 t, %1; cvt.u32.u64 %0, t; }" : "=r"(a) : "l"(p));
    return a;
}
__device__ __forceinline__ void cp16(uint32_t d, const void* s) {
    asm volatile("cp.async.cg.shared.global [%0], [%1], 16;" :: "r"(d), "l"(s) : "memory");
}
#define CP_COMMIT() asm volatile("cp.async.commit_group;" ::: "memory")
__device__ __forceinline__ void ldm_x4(uint32_t* d, uint32_t a) {
    asm volatile("ldmatrix.sync.aligned.m8n8.x4.shared.b16 {%0,%1,%2,%3}, [%4];"
        : "=r"(d[0]), "=r"(d[1]), "=r"(d[2]), "=r"(d[3]) : "r"(a));
}
__device__ __forceinline__ void ldm_x4t(uint32_t* d, uint32_t a) {
    asm volatile("ldmatrix.sync.aligned.m8n8.x4.trans.shared.b16 {%0,%1,%2,%3}, [%4];"
        : "=r"(d[0]), "=r"(d[1]), "=r"(d[2]), "=r"(d[3]) : "r"(a));
}
__device__ __forceinline__ void mma16816(float* c, const uint32_t* a, const uint32_t* b) {
    asm volatile("mma.sync.aligned.m16n8k16.row.col.f32.bf16.bf16.f32 "
        "{%0,%1,%2,%3}, {%4,%5,%6,%7}, {%8,%9}, {%0,%1,%2,%3};"
        : "+f"(c[0]), "+f"(c[1]), "+f"(c[2]), "+f"(c[3])
        : "r"(a[0]), "r"(a[1]), "r"(a[2]), "r"(a[3]), "r"(b[0]), "r"(b[1]));
}
__device__ __forceinline__ uint32_t pack2bf(float a, float b) {
    __nv_bfloat16 ha = __float2bfloat16(a), hb = __float2bfloat16(b);
    return (uint32_t)__bfloat16_as_ushort(ha) | ((uint32_t)__bfloat16_as_ushort(hb) << 16);
}
__device__ __forceinline__ void split2(float2 v, uint32_t& hw, uint32_t& lw) {
    __nv_bfloat16 h0 = __float2bfloat16(v.x), h1 = __float2bfloat16(v.y);
    hw = (uint32_t)__bfloat16_as_ushort(h0) | ((uint32_t)__bfloat16_as_ushort(h1) << 16);
    lw = pack2bf(v.x - __bfloat162float(h0), v.y - __bfloat162float(h1));
}

/* load next K/V tile into registers (4 float4 each) */
__device__ __forceinline__ void ldg_kv(const float4* Ks, const float4* Vs, int tid,
                                       float4* kr, float4* vr) {
    #pragma unroll
    for (int i = 0; i < 4; ++i) { kr[i] = Ks[tid + 256 * i]; vr[i] = Vs[tid + 256 * i]; }
}
/* split + store K/V registers into a conv buffer */
__device__ __forceinline__ void sts_kv(char* smem, uint32_t cb, int tid,
                                       const float4* kr, const float4* vr) {
    #pragma unroll
    for (int i = 0; i < 4; ++i) {
        int idx = tid + 256 * i;
        int row = idx >> 4, dp4 = idx & 15;
        uint32_t off = SWZ((uint32_t)(row * 128 + dp4 * 8));
        uint32_t h0, l0, h1, l1;
        split2(make_float2(kr[i].x, kr[i].y), h0, l0);
        split2(make_float2(kr[i].z, kr[i].w), h1, l1);
        *(uint2*)(smem + cb + OFFC_KHI + off) = make_uint2(h0, h1);
        *(uint2*)(smem + cb + OFFC_KLO + off) = make_uint2(l0, l1);
        split2(make_float2(vr[i].x, vr[i].y), h0, l0);
        split2(make_float2(vr[i].z, vr[i].w), h1, l1);
        *(uint2*)(smem + cb + OFFC_VHI + off) = make_uint2(h0, h1);
        *(uint2*)(smem + cb + OFFC_VLO + off) = make_uint2(l0, l1);
    }
}

/* ============================ main kernel ============================ */
__global__ __launch_bounds__(NTHREADS, 1)
void attn_mma_kernel(const float* __restrict__ Qg, const float* __restrict__ Kg,
                     const float* __restrict__ Vg,
                     const int* __restrict__ qmask, const int* __restrict__ kmask,
                     const int* __restrict__ gmask,
                     float* __restrict__ out_av, float* __restrict__ out_attn)
{
    extern __shared__ char smem[];
    const uint32_t sb = smem_u32(smem);
    float* sL = (float*)(smem + OFF_SL);

    const int tid  = threadIdx.x;
    const int warp = tid >> 5;
    const int lane = tid & 31;
    const int l16  = lane & 15;
    const int qg   = lane & 3;
    const int r    = lane >> 2;
    const int b    = blockIdx.y;
    const int q0   = blockIdx.x * 128;

    const int* kmb = kmask + (size_t)b * LKS;
    const int* gm0 = gmask + ((size_t)(b * LQS + q0)) * LKS;
    const float4* Kbase = (const float4*)(Kg + ((size_t)(b * LKS)) * DIMS);
    const float4* Vbase = (const float4*)(Vg + ((size_t)(b * LKS)) * DIMS);

    /* ---- group0: kmask (whole) + gmask tile0 ---- */
    {
        cp16(sb + OFF_KM + tid * 16, kmb + tid * 4);   /* 256 x 16B = 4KB */
        for (int i = tid; i < 2048; i += NTHREADS) {
            int row = i >> 4, c = i & 15;
            cp16(sb + OFF_GM + row * 272 + c * 16, gm0 + (size_t)row * LKS + c * 4);
        }
        CP_COMMIT();
    }

    /* ---- LDG K/V tile 0 into registers ---- */
    float4 kr[4], vr[4];
    ldg_kv(Kbase, Vbase, tid, kr, vr);

    /* ---- stage Q (scaled 1/8), split hi/lo, SW128 ---- */
    {
        const float4* Qg4 = (const float4*)(Qg + ((size_t)(b * LQS + q0)) * DIMS);
        #pragma unroll
        for (int i = 0; i < 8; ++i) {
            int idx = tid + 256 * i;
            int row = idx >> 4, dp4 = idx & 15;
            float4 v = Qg4[idx];
            v.x *= 0.125f; v.y *= 0.125f; v.z *= 0.125f; v.w *= 0.125f;
            uint32_t h0, l0, h1, l1;
            split2(make_float2(v.x, v.y), h0, l0);
            split2(make_float2(v.z, v.w), h1, l1);
            uint32_t off = SWZ((uint32_t)(row * 128 + dp4 * 8));
            *(uint2*)(smem + OFF_QHI + off) = make_uint2(h0, h1);
            *(uint2*)(smem + OFF_QLO + off) = make_uint2(l0, l1);
        }
    }
    __syncthreads();

    /* ---- per-warp Q A-fragments ---- */
    uint32_t qh[4][4], ql[4][4];
    {
        const int qrow = warp * 16 + l16;
        const int cgrp = (lane >> 4) * 16;
        #pragma unroll
        for (int t = 0; t < 4; ++t) {
            uint32_t off = SWZ((uint32_t)(qrow * 128 + t * 32 + cgrp));
            ldm_x4(qh[t], sb + OFF_QHI + off);
            ldm_x4(ql[t], sb + OFF_QLO + off);
        }
    }

    /* ---- convert tile 0 into conv buf 0 ---- */
    sts_kv(smem, OFF_CONV, tid, kr, vr);
    __syncthreads();

    float oc[8][4];
    #pragma unroll
    for (int j = 0; j < 8; ++j)
        #pragma unroll
        for (int c = 0; c < 4; ++c) oc[j][c] = 0.f;
    float l0s = 0.f, l1s = 0.f;

    const int row_r  = warp * 16 + r;
    const int row_r8 = row_r + 8;
    const size_t gq_r  = (size_t)(b * LQS + q0 + row_r);
    const size_t gq_r8 = gq_r + 8;
    float* attn_r  = out_attn + gq_r  * LKS;
    float* attn_r8 = out_attn + gq_r8 * LKS;
    const int* smKM = (const int*)(smem + OFF_KM);

    #pragma unroll 1
    for (int kt = 0; kt < NTILE; ++kt) {
        const int kbase = kt * BKT;
        const uint32_t cb  = OFF_CONV + (uint32_t)((kt & 1) * CONV_BYTES);
        const uint32_t cbn = OFF_CONV + (uint32_t)(((kt + 1) & 1) * CONV_BYTES);

        /* [A] LDG next K/V + cp.async next gmask */
        if (kt + 1 < NTILE) {
            const int nb = kbase + BKT;
            ldg_kv(Kbase + nb * (DIMS / 4), Vbase + nb * (DIMS / 4), tid, kr, vr);
            const uint32_t gbuf = sb + OFF_GM + (uint32_t)(((kt + 1) & 1) * GM_BYTES);
            const int* Gs = gm0 + nb;
            for (int i = tid; i < 2048; i += NTHREADS) {
                int row = i >> 4, c = i & 15;
                cp16(gbuf + row * 272 + c * 16, Gs + (size_t)row * LKS + c * 4);
            }
            CP_COMMIT();
        }

        /* [B] S = Q K^T with bf16 EC (hi*hi + lo*hi + hi*lo) */
        float sc[8][4];
        #pragma unroll
        for (int j = 0; j < 8; ++j)
            #pragma unroll
            for (int c = 0; c < 4; ++c) sc[j][c] = 0.f;

        #pragma unroll
        for (int t = 0; t < 4; ++t) {
            #pragma unroll
            for (int jp = 0; jp < 4; ++jp) {
                uint32_t kh4[4], kl4[4];
                int krow = jp * 16 + (lane & 7) + ((lane >> 4) << 3);
                uint32_t off = SWZ((uint32_t)(krow * 128 + t * 32 + ((lane >> 3) & 1) * 16));
                ldm_x4(kh4, sb + cb + OFFC_KHI + off);
                ldm_x4(kl4, sb + cb + OFFC_KLO + off);
                mma16816(sc[2*jp],   qh[t], kh4);
                mma16816(sc[2*jp],   ql[t], kh4);
                mma16816(sc[2*jp],   qh[t], kl4);
                mma16816(sc[2*jp+1], qh[t], kh4 + 2);
                mma16816(sc[2*jp+1], ql[t], kh4 + 2);
                mma16816(sc[2*jp+1], qh[t], kl4 + 2);
            }
        }

        /* [C] gmask(kt) landed (group order) + buffer handoff */
        if (kt + 1 < NTILE) asm volatile("cp.async.wait_group 1;" ::: "memory");
        else                asm volatile("cp.async.wait_group 0;" ::: "memory");
        __syncthreads();

        /* [D] convert next tile into the other conv buffer */
        if (kt + 1 < NTILE) sts_kv(smem, cbn, tid, kr, vr);

        /* [E]+[F] per 16-key group: epilogue then PV MMAs */
        const int* smG = (const int*)(smem + OFF_GM + (size_t)((kt & 1) * GM_BYTES));
        #pragma unroll
        for (int t2 = 0; t2 < 4; ++t2) {
            uint32_t pa_h[4], pa_l[4];
            #pragma unroll
            for (int u = 0; u < 2; ++u) {
                const int j = 2 * t2 + u;
                const int c64 = j * 8 + 2 * qg;
                int2 km = *(const int2*)(smKM + kbase + c64);
                int2 g0 = *(const int2*)(smG + row_r  * 68 + c64);
                int2 g1 = *(const int2*)(smG + row_r8 * 68 + c64);
                float e0 = (km.x && g0.x) ? __expf(sc[j][0]) : 0.f;
                float e1 = (km.y && g0.y) ? __expf(sc[j][1]) : 0.f;
                float e2 = (km.x && g1.x) ? __expf(sc[j][2]) : 0.f;
                float e3 = (km.y && g1.y) ? __expf(sc[j][3]) : 0.f;
                l0s += e0 + e1; l1s += e2 + e3;
                *(float2*)(attn_r  + kbase + c64) = make_float2(e0, e1);
                *(float2*)(attn_r8 + kbase + c64) = make_float2(e2, e3);
                uint32_t hw, lw;
                split2(make_float2(e0, e1), hw, lw); pa_h[2*u]   = hw; pa_l[2*u]   = lw;
                split2(make_float2(e2, e3), hw, lw); pa_h[2*u+1] = hw; pa_l[2*u+1] = lw;
            }
            #pragma unroll
            for (int j2p = 0; j2p < 4; ++j2p) {
                uint32_t vh4[4], vl4[4];
                int vrow = t2 * 16 + (lane & 15);
                uint32_t off = SWZ((uint32_t)(vrow * 128 + j2p * 32 + (lane >> 4) * 16));
                ldm_x4t(vh4, sb + cb + OFFC_VHI + off);
                ldm_x4t(vl4, sb + cb + OFFC_VLO + off);
                mma16816(oc[2*j2p],   pa_h, vh4);
                mma16816(oc[2*j2p],   pa_h, vl4);
                mma16816(oc[2*j2p],   pa_l, vh4);
                mma16816(oc[2*j2p+1], pa_h, vh4 + 2);
                mma16816(oc[2*j2p+1], pa_h, vl4 + 2);
                mma16816(oc[2*j2p+1], pa_l, vh4 + 2);
            }
        }
        __syncthreads();
    }

    /* ---- row sums across quad lanes, inv, store attn_value ---- */
    l0s += __shfl_xor_sync(0xffffffffu, l0s, 1);
    l0s += __shfl_xor_sync(0xffffffffu, l0s, 2);
    l1s += __shfl_xor_sync(0xffffffffu, l1s, 1);
    l1s += __shfl_xor_sync(0xffffffffu, l1s, 2);
    const float inv0 = (qmask[gq_r]  != 0) ? (1.0f / l0s) : 0.0f;
    const float inv1 = (qmask[gq_r8] != 0) ? (1.0f / l1s) : 0.0f;
    if (qg == 0) { sL[row_r] = inv0; sL[row_r8] = inv1; }

    {
        float* av_r  = out_av + gq_r  * DIMS;
        float* av_r8 = out_av + gq_r8 * DIMS;
        #pragma unroll
        for (int j2 = 0; j2 < 8; ++j2) {
            const int col = j2 * 8 + 2 * qg;
            *(float2*)(av_r  + col) = make_float2(oc[j2][0] * inv0, oc[j2][1] * inv0);
            *(float2*)(av_r8 + col) = make_float2(oc[j2][2] * inv1, oc[j2][3] * inv1);
        }
    }

    /* ---- fused normalize of this CTA's attn rows (L2-resident) ---- */
    __threadfence_block();
    __syncthreads();
    {
        float4* base = (float4*)(out_attn + ((size_t)(b * LQS + q0)) * LKS);
        for (int i = tid; i < 128 * 256; i += NTHREADS) {
            const float inv = sL[i >> 8];
            float4 v = base[i];
            v.x *= inv; v.y *= inv; v.z *= inv; v.w *= inv;
            base[i] = v;
        }
    }
}

extern "C" void kernel_launch(void* const* d_in, const int* in_sizes, int n_in,
                              void* d_out, int out_size) {
    const float* Q  = (const float*)d_in[0];
    const float* K  = (const float*)d_in[1];
    const float* V  = (const float*)d_in[2];
    const int*   qm = (const int*)d_in[3];
    const int*   km = (const int*)d_in[4];
    const int*   mk = (const int*)d_in[5];

    const long long NAV = (long long)BATCH * LQS * DIMS;
    float* out  = (float*)d_out;
    float* av   = out;
    float* attn = out + NAV;
    (void)out_size; (void)in_sizes; (void)n_in;

    cudaFuncSetAttribute(attn_mma_kernel, cudaFuncAttributeMaxDynamicSharedMemorySize,
                         SMEM_BYTES);
    dim3 grid(LQS / 128, BATCH);
    attn_mma_kernel<<<grid, NTHREADS, SMEM_BYTES>>>(Q, K, V, qm, km, mk, av, attn);
}